// round 1
// baseline (speedup 1.0000x reference)
#include <cuda_runtime.h>
#include <math.h>
#include <stdint.h>

#define NEXP 8
#define NTOK 16384
#define DDIM 512
#define HDIM 1408
#define CAP  16384          // worst-case tokens per expert
#define NSLOT (NTOK * 2)    // total routed slots (top-2)

// ---- device scratch (static: no allocations allowed) ----
__device__ int   g_counts[NEXP];
__device__ int   g_offsets[NEXP];
__device__ float g_usage[NEXP];
__device__ int   g_tok[NEXP * CAP];
__device__ float g_wt[NEXP * CAP];
__device__ float g_h[(size_t)NSLOT * HDIM];   // ~185 MB scratch for hidden acts

// ============================================================
// zero counters
// ============================================================
__global__ void k_zero_state() {
    int t = threadIdx.x;
    if (t < NEXP) { g_counts[t] = 0; g_usage[t] = 0.f; }
}

__global__ void k_zero_out(float* out, int n) {
    int i = blockIdx.x * blockDim.x + threadIdx.x;
    if (i < n) out[i] = 0.f;
}

// ============================================================
// router: one warp per token. softmax over 8 logits, top-2,
// renormalize, append to per-expert lists, accumulate usage.
// ============================================================
__global__ __launch_bounds__(256) void k_router(
    const float* __restrict__ x, const float* __restrict__ rw)
{
    __shared__ float rws[NEXP * DDIM];   // 16 KB
    __shared__ float su[NEXP];

    int tid = threadIdx.x;
    // load router weights (4096 floats / 256 threads = 16 each, float4)
    for (int i = tid; i < NEXP * DDIM / 4; i += 256)
        ((float4*)rws)[i] = ((const float4*)rw)[i];
    if (tid < NEXP) su[tid] = 0.f;
    __syncthreads();

    int warp = tid >> 5, lane = tid & 31;
    int token = blockIdx.x * 8 + warp;
    const float* xt = x + (size_t)token * DDIM;

    float p[NEXP];
#pragma unroll
    for (int e = 0; e < NEXP; e++) p[e] = 0.f;

    for (int d = lane; d < DDIM; d += 32) {
        float xv = xt[d];
#pragma unroll
        for (int e = 0; e < NEXP; e++) p[e] = fmaf(xv, rws[e * DDIM + d], p[e]);
    }
#pragma unroll
    for (int off = 16; off > 0; off >>= 1)
#pragma unroll
        for (int e = 0; e < NEXP; e++) p[e] += __shfl_xor_sync(0xffffffffu, p[e], off);

    if (lane == 0) {
        float m = p[0];
#pragma unroll
        for (int e = 1; e < NEXP; e++) m = fmaxf(m, p[e]);
        float s = 0.f;
#pragma unroll
        for (int e = 0; e < NEXP; e++) { p[e] = expf(p[e] - m); s += p[e]; }
        float inv = 1.f / s;
#pragma unroll
        for (int e = 0; e < NEXP; e++) {
            p[e] *= inv;
            atomicAdd(&su[e], p[e]);
        }
        // top-2 (first index wins ties, matching lax.top_k)
        int i1 = 0;
#pragma unroll
        for (int e = 1; e < NEXP; e++) if (p[e] > p[i1]) i1 = e;
        int i2 = (i1 == 0) ? 1 : 0;
#pragma unroll
        for (int e = 0; e < NEXP; e++) if (e != i1 && p[e] > p[i2]) i2 = e;

        float denom = p[i1] + p[i2];
        float w1 = p[i1] / denom, w2 = p[i2] / denom;

        int s1 = atomicAdd(&g_counts[i1], 1);
        g_tok[i1 * CAP + s1] = token; g_wt[i1 * CAP + s1] = w1;
        int s2 = atomicAdd(&g_counts[i2], 1);
        g_tok[i2 * CAP + s2] = token; g_wt[i2 * CAP + s2] = w2;
    }
    __syncthreads();
    if (tid < NEXP) atomicAdd(&g_usage[tid], su[tid]);
}

// ============================================================
// prefix offsets + aux loss
// ============================================================
__global__ void k_prefix_aux(float* out, int out_size) {
    int off = 0;
    float s = 0.f;
    for (int e = 0; e < NEXP; e++) {
        g_offsets[e] = off;
        off += g_counts[e];
        float u = g_usage[e] * (1.f / (float)NTOK);
        s += u * u;
    }
    out[out_size - 1] = 8.f * s * 0.01f;
}

// ============================================================
// Pass A: h = silu(Xg @ w1[e]^T) * (Xg @ w3[e]^T)
// tile: 128 tokens x 64 h-cols, K-chunk 16 over D=512
// grid: (H/64=22, 128 m-tiles, 8 experts), 256 threads
// ============================================================
#define TM 128
#define TN 64
#define KC 16

__global__ __launch_bounds__(256) void k_passA(
    const float* __restrict__ x,
    const float* __restrict__ w1, const float* __restrict__ w3)
{
    int e   = blockIdx.z;
    int cnt = g_counts[e];
    int m0  = blockIdx.y * TM;
    if (m0 >= cnt) return;
    int n0  = blockIdx.x * TN;
    int eoff = g_offsets[e];

    __shared__ float xs[TM][KC];
    __shared__ float w1s[KC][TN + 4];
    __shared__ float w3s[KC][TN + 4];
    __shared__ int   toks[TM];

    int tid = threadIdx.x;
    if (tid < TM) {
        int r = m0 + tid;
        toks[tid] = (r < cnt) ? g_tok[e * CAP + r] : -1;
    }
    __syncthreads();

    int tx = tid & 15, ty = tid >> 4;

    float acc1[8][4], acc3[8][4];
#pragma unroll
    for (int i = 0; i < 8; i++)
#pragma unroll
        for (int j = 0; j < 4; j++) { acc1[i][j] = 0.f; acc3[i][j] = 0.f; }

    const float* w1e = w1 + (size_t)e * HDIM * DDIM;
    const float* w3e = w3 + (size_t)e * HDIM * DDIM;

    for (int k0 = 0; k0 < DDIM; k0 += KC) {
        // X tile: 128x16, gathered rows (512 float4 / 256 thr = 2 each)
#pragma unroll
        for (int i = 0; i < 2; i++) {
            int li = tid * 2 + i;
            int r = li >> 2, c = li & 3;
            int t = toks[r];
            float4 v = make_float4(0.f, 0.f, 0.f, 0.f);
            if (t >= 0) v = *(const float4*)&x[(size_t)t * DDIM + k0 + c * 4];
            *(float4*)&xs[r][c * 4] = v;
        }
        // W tiles transposed into [k][h]
        {
            int h = tid >> 2, c = tid & 3;
            const float4 a = *(const float4*)&w1e[(size_t)(n0 + h) * DDIM + k0 + c * 4];
            w1s[c*4+0][h] = a.x; w1s[c*4+1][h] = a.y; w1s[c*4+2][h] = a.z; w1s[c*4+3][h] = a.w;
            const float4 b = *(const float4*)&w3e[(size_t)(n0 + h) * DDIM + k0 + c * 4];
            w3s[c*4+0][h] = b.x; w3s[c*4+1][h] = b.y; w3s[c*4+2][h] = b.z; w3s[c*4+3][h] = b.w;
        }
        __syncthreads();
#pragma unroll
        for (int k = 0; k < KC; k++) {
            float xr[8];
#pragma unroll
            for (int i = 0; i < 8; i++) xr[i] = xs[ty * 8 + i][k];
            float4 wa = *(const float4*)&w1s[k][tx * 4];
            float4 wb = *(const float4*)&w3s[k][tx * 4];
#pragma unroll
            for (int i = 0; i < 8; i++) {
                acc1[i][0] = fmaf(xr[i], wa.x, acc1[i][0]);
                acc1[i][1] = fmaf(xr[i], wa.y, acc1[i][1]);
                acc1[i][2] = fmaf(xr[i], wa.z, acc1[i][2]);
                acc1[i][3] = fmaf(xr[i], wa.w, acc1[i][3]);
                acc3[i][0] = fmaf(xr[i], wb.x, acc3[i][0]);
                acc3[i][1] = fmaf(xr[i], wb.y, acc3[i][1]);
                acc3[i][2] = fmaf(xr[i], wb.z, acc3[i][2]);
                acc3[i][3] = fmaf(xr[i], wb.w, acc3[i][3]);
            }
        }
        __syncthreads();
    }

    // epilogue: silu(a)*b -> g_h
#pragma unroll
    for (int i = 0; i < 8; i++) {
        int r = m0 + ty * 8 + i;
        if (r >= cnt) continue;
        float4 o;
        float a;
        a = acc1[i][0]; o.x = (a / (1.f + expf(-a))) * acc3[i][0];
        a = acc1[i][1]; o.y = (a / (1.f + expf(-a))) * acc3[i][1];
        a = acc1[i][2]; o.z = (a / (1.f + expf(-a))) * acc3[i][2];
        a = acc1[i][3]; o.w = (a / (1.f + expf(-a))) * acc3[i][3];
        *(float4*)&g_h[(size_t)(eoff + r) * HDIM + n0 + tx * 4] = o;
    }
}

// ============================================================
// Pass B: out[token] += wt * (h @ w2[e]^T)
// tile: 128 slots x 64 d-cols, K-chunk 16 over H=1408
// grid: (D/64=8, 128 m-tiles, 8 experts), 256 threads
// ============================================================
__global__ __launch_bounds__(256) void k_passB(
    const float* __restrict__ w2, float* __restrict__ out)
{
    int e   = blockIdx.z;
    int cnt = g_counts[e];
    int m0  = blockIdx.y * TM;
    if (m0 >= cnt) return;
    int n0  = blockIdx.x * TN;
    int eoff = g_offsets[e];

    __shared__ float hs[TM][KC];
    __shared__ float ws[KC][TN + 4];

    int tid = threadIdx.x;
    int tx = tid & 15, ty = tid >> 4;

    float acc[8][4];
#pragma unroll
    for (int i = 0; i < 8; i++)
#pragma unroll
        for (int j = 0; j < 4; j++) acc[i][j] = 0.f;

    const float* w2e = w2 + (size_t)e * DDIM * HDIM;

    for (int k0 = 0; k0 < HDIM; k0 += KC) {
#pragma unroll
        for (int i = 0; i < 2; i++) {
            int li = tid * 2 + i;
            int r = li >> 2, c = li & 3;
            float4 v = make_float4(0.f, 0.f, 0.f, 0.f);
            if (m0 + r < cnt)
                v = *(const float4*)&g_h[(size_t)(eoff + m0 + r) * HDIM + k0 + c * 4];
            *(float4*)&hs[r][c * 4] = v;
        }
        {
            int d = tid >> 2, c = tid & 3;
            const float4 a = *(const float4*)&w2e[(size_t)(n0 + d) * HDIM + k0 + c * 4];
            ws[c*4+0][d] = a.x; ws[c*4+1][d] = a.y; ws[c*4+2][d] = a.z; ws[c*4+3][d] = a.w;
        }
        __syncthreads();
#pragma unroll
        for (int k = 0; k < KC; k++) {
            float hr[8];
#pragma unroll
            for (int i = 0; i < 8; i++) hr[i] = hs[ty * 8 + i][k];
            float4 wv = *(const float4*)&ws[k][tx * 4];
#pragma unroll
            for (int i = 0; i < 8; i++) {
                acc[i][0] = fmaf(hr[i], wv.x, acc[i][0]);
                acc[i][1] = fmaf(hr[i], wv.y, acc[i][1]);
                acc[i][2] = fmaf(hr[i], wv.z, acc[i][2]);
                acc[i][3] = fmaf(hr[i], wv.w, acc[i][3]);
            }
        }
        __syncthreads();
    }

#pragma unroll
    for (int i = 0; i < 8; i++) {
        int r = m0 + ty * 8 + i;
        if (r >= cnt) continue;
        int tok  = g_tok[e * CAP + r];
        float wt = g_wt[e * CAP + r];
        float* op = &out[(size_t)tok * DDIM + n0 + tx * 4];
        atomicAdd(&op[0], acc[i][0] * wt);
        atomicAdd(&op[1], acc[i][1] * wt);
        atomicAdd(&op[2], acc[i][2] * wt);
        atomicAdd(&op[3], acc[i][3] * wt);
    }
}

// ============================================================
// launch
// ============================================================
extern "C" void kernel_launch(void* const* d_in, const int* in_sizes, int n_in,
                              void* d_out, int out_size)
{
    const float* x  = (const float*)d_in[0];
    const float* rw = (const float*)d_in[1];
    const float* w1 = (const float*)d_in[2];
    const float* w2 = (const float*)d_in[3];
    const float* w3 = (const float*)d_in[4];
    float* out = (float*)d_out;

    k_zero_out<<<(out_size + 1023) / 1024, 1024>>>(out, out_size);
    k_zero_state<<<1, 32>>>();
    k_router<<<NTOK / 8, 256>>>(x, rw);
    k_prefix_aux<<<1, 1>>>(out, out_size);
    k_passA<<<dim3(HDIM / TN, CAP / TM, NEXP), 256>>>(x, w1, w3);
    k_passB<<<dim3(DDIM / TN, CAP / TM, NEXP), 256>>>(w2, out);
}

// round 3
// speedup vs baseline: 2.1481x; 2.1481x over previous
#include <cuda_runtime.h>
#include <math.h>
#include <stdint.h>

#define NEXP 8
#define NTOK 16384
#define DDIM 512
#define HDIM 1408
#define CAP  16384
#define NSLOT (NTOK * 2)

// ---- device scratch (no allocations allowed) ----
__device__ int   g_counts[NEXP];
__device__ int   g_offsets[NEXP];
__device__ float g_usage[NEXP];
__device__ int   g_tok[NEXP * CAP];
__device__ float g_wt[NEXP * CAP];
__device__ float g_h[(size_t)NSLOT * HDIM];   // hidden activations (fp32)

// ============================================================
// helpers
// ============================================================
__device__ __forceinline__ uint32_t f2tf32(float f) {
    uint32_t r;
    asm("cvt.rna.tf32.f32 %0, %1;" : "=r"(r) : "f"(f));
    return r;
}
// D += A(16x8) * B(8x8), tf32 inputs, f32 accum
__device__ __forceinline__ void mma8(float* c, const uint32_t* a, uint32_t b0, uint32_t b1) {
    asm volatile("mma.sync.aligned.m16n8k8.row.col.f32.tf32.tf32.f32 "
                 "{%0,%1,%2,%3}, {%4,%5,%6,%7}, {%8,%9}, {%0,%1,%2,%3};"
                 : "+f"(c[0]), "+f"(c[1]), "+f"(c[2]), "+f"(c[3])
                 : "r"(a[0]), "r"(a[1]), "r"(a[2]), "r"(a[3]), "r"(b0), "r"(b1));
}
__device__ __forceinline__ float silu(float a) { return a / (1.f + __expf(-a)); }

// ============================================================
// small kernels
// ============================================================
__global__ void k_zero_state() {
    int t = threadIdx.x;
    if (t < NEXP) { g_counts[t] = 0; g_usage[t] = 0.f; }
}
__global__ void k_zero_out(float* out, int n) {
    int i = blockIdx.x * blockDim.x + threadIdx.x;
    if (i < n) out[i] = 0.f;
}

__global__ __launch_bounds__(256) void k_router(
    const float* __restrict__ x, const float* __restrict__ rw)
{
    __shared__ float rws[NEXP * DDIM];
    __shared__ float su[NEXP];
    int tid = threadIdx.x;
    for (int i = tid; i < NEXP * DDIM / 4; i += 256)
        ((float4*)rws)[i] = ((const float4*)rw)[i];
    if (tid < NEXP) su[tid] = 0.f;
    __syncthreads();

    int warp = tid >> 5, lane = tid & 31;
    int token = blockIdx.x * 8 + warp;
    const float* xt = x + (size_t)token * DDIM;

    float p[NEXP];
#pragma unroll
    for (int e = 0; e < NEXP; e++) p[e] = 0.f;
    for (int d = lane; d < DDIM; d += 32) {
        float xv = xt[d];
#pragma unroll
        for (int e = 0; e < NEXP; e++) p[e] = fmaf(xv, rws[e * DDIM + d], p[e]);
    }
#pragma unroll
    for (int off = 16; off > 0; off >>= 1)
#pragma unroll
        for (int e = 0; e < NEXP; e++) p[e] += __shfl_xor_sync(0xffffffffu, p[e], off);

    if (lane == 0) {
        float m = p[0];
#pragma unroll
        for (int e = 1; e < NEXP; e++) m = fmaxf(m, p[e]);
        float s = 0.f;
#pragma unroll
        for (int e = 0; e < NEXP; e++) { p[e] = expf(p[e] - m); s += p[e]; }
        float inv = 1.f / s;
#pragma unroll
        for (int e = 0; e < NEXP; e++) { p[e] *= inv; atomicAdd(&su[e], p[e]); }
        int i1 = 0;
#pragma unroll
        for (int e = 1; e < NEXP; e++) if (p[e] > p[i1]) i1 = e;
        int i2 = (i1 == 0) ? 1 : 0;
#pragma unroll
        for (int e = 0; e < NEXP; e++) if (e != i1 && p[e] > p[i2]) i2 = e;
        float denom = p[i1] + p[i2];
        float w1 = p[i1] / denom, w2 = p[i2] / denom;
        int s1 = atomicAdd(&g_counts[i1], 1);
        g_tok[i1 * CAP + s1] = token; g_wt[i1 * CAP + s1] = w1;
        int s2 = atomicAdd(&g_counts[i2], 1);
        g_tok[i2 * CAP + s2] = token; g_wt[i2 * CAP + s2] = w2;
    }
    __syncthreads();
    if (tid < NEXP) atomicAdd(&g_usage[tid], su[tid]);
}

__global__ void k_prefix_aux(float* out, int out_size) {
    int off = 0;
    float s = 0.f;
    for (int e = 0; e < NEXP; e++) {
        g_offsets[e] = off;
        off += g_counts[e];
        float u = g_usage[e] * (1.f / (float)NTOK);
        s += u * u;
    }
    out[out_size - 1] = 8.f * s * 0.01f;
}

// ============================================================
// Pass A (mma.sync tf32): h = silu(Xg @ w1^T) * (Xg @ w3^T)
// block tile: M=128 tokens x N=64 h-cols (both matrices), K-chunk 32
// 8 warps, warp tile 32x32 per matrix = 2x4 m16n8k8 tiles
// ============================================================
#define STR 40   // smem row stride (floats): conflict-free frag loads, 16B aligned

__global__ __launch_bounds__(256) void k_passA(
    const float* __restrict__ x,
    const float* __restrict__ w1, const float* __restrict__ w3)
{
    int e   = blockIdx.z;
    int cnt = g_counts[e];
    int m0  = blockIdx.y * 128;
    if (m0 >= cnt) return;
    int n0  = blockIdx.x * 64;
    int eoff = g_offsets[e];

    __shared__ __align__(16) float As[128 * STR];
    __shared__ __align__(16) float B1s[64 * STR];
    __shared__ __align__(16) float B3s[64 * STR];
    __shared__ int toks[128];

    int tid = threadIdx.x;
    int warp = tid >> 5, lane = tid & 31;
    int g = lane >> 2, t4 = lane & 3;
    int wm = warp >> 1, wn = warp & 1;   // warp tile: rows wm*32, cols wn*32

    if (tid < 128) {
        int r = m0 + tid;
        toks[tid] = (r < cnt) ? g_tok[e * CAP + r] : -1;
    }
    __syncthreads();

    const float* w1e = w1 + (size_t)e * HDIM * DDIM;
    const float* w3e = w3 + (size_t)e * HDIM * DDIM;

    float acc1[2][4][4], acc3[2][4][4];
#pragma unroll
    for (int i = 0; i < 2; i++)
#pragma unroll
        for (int j = 0; j < 4; j++)
#pragma unroll
            for (int q = 0; q < 4; q++) { acc1[i][j][q] = 0.f; acc3[i][j][q] = 0.f; }

    // prefetch registers
    float4 pa[4], pb1[2], pb3[2];
    int ar[4], ac[4], br[2], bc[2];
#pragma unroll
    for (int i = 0; i < 4; i++) { int idx = i * 256 + tid; ar[i] = idx >> 3; ac[i] = (idx & 7) * 4; }
#pragma unroll
    for (int i = 0; i < 2; i++) { int idx = i * 256 + tid; br[i] = idx >> 3; bc[i] = (idx & 7) * 4; }

    auto load_chunk = [&](int k0) {
#pragma unroll
        for (int i = 0; i < 4; i++) {
            int t = toks[ar[i]];
            pa[i] = make_float4(0.f, 0.f, 0.f, 0.f);
            if (t >= 0) pa[i] = *(const float4*)(x + (size_t)t * DDIM + k0 + ac[i]);
        }
#pragma unroll
        for (int i = 0; i < 2; i++) {
            pb1[i] = *(const float4*)(w1e + (size_t)(n0 + br[i]) * DDIM + k0 + bc[i]);
            pb3[i] = *(const float4*)(w3e + (size_t)(n0 + br[i]) * DDIM + k0 + bc[i]);
        }
    };
    auto store_chunk = [&]() {
#pragma unroll
        for (int i = 0; i < 4; i++) {
            uint4 v = { f2tf32(pa[i].x), f2tf32(pa[i].y), f2tf32(pa[i].z), f2tf32(pa[i].w) };
            *(uint4*)&As[ar[i] * STR + ac[i]] = v;
        }
#pragma unroll
        for (int i = 0; i < 2; i++) {
            uint4 v1 = { f2tf32(pb1[i].x), f2tf32(pb1[i].y), f2tf32(pb1[i].z), f2tf32(pb1[i].w) };
            *(uint4*)&B1s[br[i] * STR + bc[i]] = v1;
            uint4 v3 = { f2tf32(pb3[i].x), f2tf32(pb3[i].y), f2tf32(pb3[i].z), f2tf32(pb3[i].w) };
            *(uint4*)&B3s[br[i] * STR + bc[i]] = v3;
        }
    };

    load_chunk(0);
    const int NCH = DDIM / 32;
    for (int kc = 0; kc < NCH; kc++) {
        if (kc > 0) __syncthreads();
        store_chunk();
        __syncthreads();
        if (kc + 1 < NCH) load_chunk((kc + 1) * 32);

#pragma unroll
        for (int ks = 0; ks < 4; ks++) {
            int k = ks * 8 + t4;
            uint32_t a[2][4];
#pragma unroll
            for (int mi = 0; mi < 2; mi++) {
                int row = wm * 32 + mi * 16 + g;
                a[mi][0] = __float_as_uint(As[row * STR + k]);
                a[mi][1] = __float_as_uint(As[(row + 8) * STR + k]);
                a[mi][2] = __float_as_uint(As[row * STR + k + 4]);
                a[mi][3] = __float_as_uint(As[(row + 8) * STR + k + 4]);
            }
#pragma unroll
            for (int ni = 0; ni < 4; ni++) {
                int bn = wn * 32 + ni * 8 + g;
                uint32_t b1a = __float_as_uint(B1s[bn * STR + k]);
                uint32_t b1b = __float_as_uint(B1s[bn * STR + k + 4]);
                uint32_t b3a = __float_as_uint(B3s[bn * STR + k]);
                uint32_t b3b = __float_as_uint(B3s[bn * STR + k + 4]);
#pragma unroll
                for (int mi = 0; mi < 2; mi++) {
                    mma8(acc1[mi][ni], a[mi], b1a, b1b);
                    mma8(acc3[mi][ni], a[mi], b3a, b3b);
                }
            }
        }
    }

    // epilogue: silu(acc1)*acc3 -> g_h
#pragma unroll
    for (int mi = 0; mi < 2; mi++) {
        int r0 = m0 + wm * 32 + mi * 16 + g;
        int r1 = r0 + 8;
        size_t b0 = (size_t)(eoff + r0) * HDIM + n0;
        size_t b1 = (size_t)(eoff + r1) * HDIM + n0;
#pragma unroll
        for (int ni = 0; ni < 4; ni++) {
            int col = wn * 32 + ni * 8 + t4 * 2;
            if (r0 < cnt) {
                float2 o = { silu(acc1[mi][ni][0]) * acc3[mi][ni][0],
                             silu(acc1[mi][ni][1]) * acc3[mi][ni][1] };
                *(float2*)(g_h + b0 + col) = o;
            }
            if (r1 < cnt) {
                float2 o = { silu(acc1[mi][ni][2]) * acc3[mi][ni][2],
                             silu(acc1[mi][ni][3]) * acc3[mi][ni][3] };
                *(float2*)(g_h + b1 + col) = o;
            }
        }
    }
}

// ============================================================
// Pass B (mma.sync tf32): out[token] += wt * (h @ w2^T)
// block tile: M=128 slots x N=64 d-cols, K-chunk 32 over H=1408
// ============================================================
__global__ __launch_bounds__(256) void k_passB(
    const float* __restrict__ w2, float* __restrict__ out)
{
    int e   = blockIdx.z;
    int cnt = g_counts[e];
    int m0  = blockIdx.y * 128;
    if (m0 >= cnt) return;
    int n0  = blockIdx.x * 64;
    int eoff = g_offsets[e];

    __shared__ __align__(16) float As[128 * STR];
    __shared__ __align__(16) float Bs[64 * STR];

    int tid = threadIdx.x;
    int warp = tid >> 5, lane = tid & 31;
    int g = lane >> 2, t4 = lane & 3;
    int wm = warp >> 1, wn = warp & 1;

    const float* w2e = w2 + (size_t)e * DDIM * HDIM;

    float acc[2][4][4];
#pragma unroll
    for (int i = 0; i < 2; i++)
#pragma unroll
        for (int j = 0; j < 4; j++)
#pragma unroll
            for (int q = 0; q < 4; q++) acc[i][j][q] = 0.f;

    float4 pa[4], pb[2];
    int ar[4], ac[4], br[2], bc[2];
#pragma unroll
    for (int i = 0; i < 4; i++) { int idx = i * 256 + tid; ar[i] = idx >> 3; ac[i] = (idx & 7) * 4; }
#pragma unroll
    for (int i = 0; i < 2; i++) { int idx = i * 256 + tid; br[i] = idx >> 3; bc[i] = (idx & 7) * 4; }

    auto load_chunk = [&](int k0) {
#pragma unroll
        for (int i = 0; i < 4; i++) {
            pa[i] = make_float4(0.f, 0.f, 0.f, 0.f);
            if (m0 + ar[i] < cnt)
                pa[i] = *(const float4*)(g_h + (size_t)(eoff + m0 + ar[i]) * HDIM + k0 + ac[i]);
        }
#pragma unroll
        for (int i = 0; i < 2; i++)
            pb[i] = *(const float4*)(w2e + (size_t)(n0 + br[i]) * HDIM + k0 + bc[i]);
    };
    auto store_chunk = [&]() {
#pragma unroll
        for (int i = 0; i < 4; i++) {
            uint4 v = { f2tf32(pa[i].x), f2tf32(pa[i].y), f2tf32(pa[i].z), f2tf32(pa[i].w) };
            *(uint4*)&As[ar[i] * STR + ac[i]] = v;
        }
#pragma unroll
        for (int i = 0; i < 2; i++) {
            uint4 v = { f2tf32(pb[i].x), f2tf32(pb[i].y), f2tf32(pb[i].z), f2tf32(pb[i].w) };
            *(uint4*)&Bs[br[i] * STR + bc[i]] = v;
        }
    };

    load_chunk(0);
    const int NCH = HDIM / 32;
    for (int kc = 0; kc < NCH; kc++) {
        if (kc > 0) __syncthreads();
        store_chunk();
        __syncthreads();
        if (kc + 1 < NCH) load_chunk((kc + 1) * 32);

#pragma unroll
        for (int ks = 0; ks < 4; ks++) {
            int k = ks * 8 + t4;
            uint32_t a[2][4];
#pragma unroll
            for (int mi = 0; mi < 2; mi++) {
                int row = wm * 32 + mi * 16 + g;
                a[mi][0] = __float_as_uint(As[row * STR + k]);
                a[mi][1] = __float_as_uint(As[(row + 8) * STR + k]);
                a[mi][2] = __float_as_uint(As[row * STR + k + 4]);
                a[mi][3] = __float_as_uint(As[(row + 8) * STR + k + 4]);
            }
#pragma unroll
            for (int ni = 0; ni < 4; ni++) {
                int bn = wn * 32 + ni * 8 + g;
                uint32_t b0 = __float_as_uint(Bs[bn * STR + k]);
                uint32_t b1 = __float_as_uint(Bs[bn * STR + k + 4]);
#pragma unroll
                for (int mi = 0; mi < 2; mi++)
                    mma8(acc[mi][ni], a[mi], b0, b1);
            }
        }
    }

    // epilogue: weighted atomic scatter
#pragma unroll
    for (int mi = 0; mi < 2; mi++) {
        int r0 = m0 + wm * 32 + mi * 16 + g;
        int r1 = r0 + 8;
        int tok0 = 0, tok1 = 0; float wt0 = 0.f, wt1 = 0.f;
        if (r0 < cnt) { tok0 = g_tok[e * CAP + r0]; wt0 = g_wt[e * CAP + r0]; }
        if (r1 < cnt) { tok1 = g_tok[e * CAP + r1]; wt1 = g_wt[e * CAP + r1]; }
#pragma unroll
        for (int ni = 0; ni < 4; ni++) {
            int col = n0 + wn * 32 + ni * 8 + t4 * 2;
            if (r0 < cnt) {
                atomicAdd(out + (size_t)tok0 * DDIM + col,     acc[mi][ni][0] * wt0);
                atomicAdd(out + (size_t)tok0 * DDIM + col + 1, acc[mi][ni][1] * wt0);
            }
            if (r1 < cnt) {
                atomicAdd(out + (size_t)tok1 * DDIM + col,     acc[mi][ni][2] * wt1);
                atomicAdd(out + (size_t)tok1 * DDIM + col + 1, acc[mi][ni][3] * wt1);
            }
        }
    }
}

// ============================================================
// launch
// ============================================================
extern "C" void kernel_launch(void* const* d_in, const int* in_sizes, int n_in,
                              void* d_out, int out_size)
{
    const float* x  = (const float*)d_in[0];
    const float* rw = (const float*)d_in[1];
    const float* w1 = (const float*)d_in[2];
    const float* w2 = (const float*)d_in[3];
    const float* w3 = (const float*)d_in[4];
    float* out = (float*)d_out;

    k_zero_out<<<(out_size + 1023) / 1024, 1024>>>(out, out_size);
    k_zero_state<<<1, 32>>>();
    k_router<<<NTOK / 8, 256>>>(x, rw);
    k_prefix_aux<<<1, 1>>>(out, out_size);
    k_passA<<<dim3(HDIM / 64, CAP / 128, NEXP), 256>>>(x, w1, w3);
    k_passB<<<dim3(DDIM / 64, CAP / 128, NEXP), 256>>>(w2, out);
}